// round 17
// baseline (speedup 1.0000x reference)
#include <cuda_runtime.h>

#define NG      1024
#define IMG_W   256
#define IMG_H   256
#define TILE_SZ 64
#define FOCALF  256.0f
#define LOG2E   1.4426950408889634f

#define BLK_W   16
#define BLK_H   16
#define PAD     1.0f
#define CULLF   0.7f    // circle cull at 3.5 sigma (tile mask stays exact 5 sigma)
#define NBLK    ((IMG_W / BLK_W) * (IMG_H / BLK_H))   // 256
#define NTHR    512
#define NPX     (BLK_W * BLK_H)                        // 256

__device__ __forceinline__ float frcp(float x) {
    float r; asm("rcp.approx.ftz.f32 %0, %1;" : "=f"(r) : "f"(x)); return r;
}
__device__ __forceinline__ float flg2(float x) {
    float r; asm("lg2.approx.f32 %0, %1;" : "=f"(r) : "f"(x)); return r;
}
__device__ __forceinline__ float fex2(float x) {
    float r; asm("ex2.approx.ftz.f32 %0, %1;" : "=f"(r) : "f"(x)); return r;
}

__global__ void __launch_bounds__(NTHR, 2) k_fused(
        const float* __restrict__ means3d,
        const float* __restrict__ opacity,
        const float* __restrict__ scale3d,
        const float* __restrict__ features,
        const float* __restrict__ V,
        const float* __restrict__ P,
        float* __restrict__ out) {

    __shared__ float4 sA[NG + 1];                // (mx, my, k2, lg2(op)) + sentinel
    __shared__ float4 sB[NG + 1];                // (r, g, b, depth)      + sentinel
    __shared__ unsigned long long sKey[NG];
    __shared__ float M[16];
    __shared__ int s_cnt;

    const int tid  = threadIdx.x;
    const int lane = tid & 31;

    // fused projection coefficients (ph0, ph1, ph3, tz) per (x,y,z,1)
    if (tid < 16) {
        int r = tid & 3, c = tid >> 2;
        float mm;
        if (c < 3) {
            int pc = (c == 2) ? 3 : c;
            mm = V[r*4+0]*P[0*4+pc] + V[r*4+1]*P[1*4+pc]
               + V[r*4+2]*P[2*4+pc] + V[r*4+3]*P[3*4+pc];
        } else {
            mm = V[r*4+2];
        }
        M[c*4 + r] = mm;
    }
    if (tid == 0) s_cnt = 0;

    const int bx = blockIdx.x & 15;
    const int by = blockIdx.x >> 4;
    const int x0 = bx * BLK_W;
    const int y0 = by * BLK_H;

    const float tu0 = (float)((x0 / TILE_SZ) * TILE_SZ);
    const float tv0 = (float)((y0 / TILE_SZ) * TILE_SZ);
    const float tu1 = tu0 + (float)TILE_SZ - 1.0f;
    const float tv1 = tv0 + (float)TILE_SZ - 1.0f;
    const float cx = (float)x0 + (BLK_W - 1) * 0.5f;
    const float cy = (float)y0 + (BLK_H - 1) * 0.5f;
    const float hw = (BLK_W - 1) * 0.5f + PAD;
    const float hh = (BLK_H - 1) * 0.5f + PAD;

    // prefetch both gaussians owned by this thread (overlaps M LDG chain)
    const int g0 = tid, g1 = tid + NTHR;
    float x_0 = means3d[3*g0+0], y_0 = means3d[3*g0+1], z_0 = means3d[3*g0+2];
    float x_1 = means3d[3*g1+0], y_1 = means3d[3*g1+1], z_1 = means3d[3*g1+2];
    float sc0 = scale3d[g0],  sc1 = scale3d[g1];
    float op0 = opacity[g0],  op1 = opacity[g1];
    float fr0 = features[3*g0+0], fg0 = features[3*g0+1], fb0 = features[3*g0+2];
    float fr1 = features[3*g1+0], fg1 = features[3*g1+1], fb1 = features[3*g1+2];

    __syncthreads();                              // M ready

    float4 A0, B0, A1, B1;
    unsigned long long k0 = 0, k1 = 0;
    bool m0, m1;
    unsigned bal0 = 0, bal1 = 0;

    #pragma unroll
    for (int it = 0; it < 2; it++) {
        float x = it ? x_1 : x_0, y = it ? y_1 : y_0, z = it ? z_1 : z_0;
        float sc = it ? sc1 : sc0, op = it ? op1 : op0;

        float ph0 = fmaf(x, M[0],  fmaf(y, M[1],  fmaf(z, M[2],  M[3])));
        float ph1 = fmaf(x, M[4],  fmaf(y, M[5],  fmaf(z, M[6],  M[7])));
        float ph3 = fmaf(x, M[8],  fmaf(y, M[9],  fmaf(z, M[10], M[11])));
        float tz  = fmaf(x, M[12], fmaf(y, M[13], fmaf(z, M[14], M[15])));

        float invw = frcp(ph3 + 1e-6f);
        float mx = fmaf(ph0 * invw, 128.0f, 127.5f);
        float my = fmaf(ph1 * invw, 128.0f, 127.5f);

        float rtz   = frcp(tz);
        float s2    = sc * FOCALF * rtz;
        float radii = 5.0f * s2;
        float rs2   = frcp(s2);
        float k2    = (-0.5f * LOG2E) * rs2 * rs2;

        // exact reference tile mask (5 sigma, unclamped equivalent for strict >)
        bool mTile = (fminf(mx + radii, tu1) > fmaxf(mx - radii, tu0)) &&
                     (fminf(my + radii, tv1) > fmaxf(my - radii, tv0));
        // circle-distance cull at 3.5 sigma + PAD
        float rc  = CULLF * radii;
        float ddx = fmaxf(fabsf(mx - cx) - hw, 0.0f);
        float ddy = fmaxf(fabsf(my - cy) - hh, 0.0f);
        bool mm = mTile && (fmaf(ddx, ddx, ddy * ddy) < rc * rc);

        unsigned bal = __ballot_sync(0xffffffffu, mm);
        if (mm) {
            int prefix = __popc(bal & ((1u << lane) - 1u));
            int leader = __ffs(bal) - 1;
            int wbase = 0;
            if (lane == leader) wbase = atomicAdd(&s_cnt, __popc(bal));
            wbase = __shfl_sync(bal, wbase, leader);
            unsigned ku = __float_as_uint(tz);
            ku = (ku & 0x80000000u) ? ~ku : (ku | 0x80000000u);
            unsigned long long kk =
                ((unsigned long long)ku << 32) | (unsigned)(it ? g1 : g0);
            sKey[wbase + prefix] = kk;
            float lop = flg2(op);
            if (it == 0) { k0 = kk; A0 = make_float4(mx, my, k2, lop);
                           B0 = make_float4(fr0, fg0, fb0, tz); }
            else         { k1 = kk; A1 = make_float4(mx, my, k2, lop);
                           B1 = make_float4(fr1, fg1, fb1, tz); }
        }
        if (it == 0) { m0 = mm; bal0 = bal; }
        else         { m1 = mm; bal1 = bal; }
    }

    __syncthreads();                              // keys ready
    const int cnt = s_cnt;

    // ---- cooperative warp rank (lanes share key scans per winner) ----
    int r0 = -1, r1 = -1;
    for (unsigned b = bal0; b; b &= b - 1) {
        int wl = __ffs(b) - 1;
        unsigned long long k = __shfl_sync(0xffffffffu, k0, wl);
        int c = 0;
        for (int j = lane; j < cnt; j += 32) c += (sKey[j] < k) ? 1 : 0;
        c = __reduce_add_sync(0xffffffffu, c);
        if (lane == wl) r0 = c;
    }
    for (unsigned b = bal1; b; b &= b - 1) {
        int wl = __ffs(b) - 1;
        unsigned long long k = __shfl_sync(0xffffffffu, k1, wl);
        int c = 0;
        for (int j = lane; j < cnt; j += 32) c += (sKey[j] < k) ? 1 : 0;
        c = __reduce_add_sync(0xffffffffu, c);
        if (lane == wl) r1 = c;
    }
    if (m0) { sA[r0] = A0; sB[r0] = B0; }
    if (m1) { sA[r1] = A1; sB[r1] = B1; }
    // sentinel: a = ex2(-huge) = 0 -> exact no-op for the odd-cnt overhang
    if (tid == 0) {
        sA[cnt] = make_float4(0.0f, 0.0f, 0.0f, -1e30f);
        sB[cnt] = make_float4(0.0f, 0.0f, 0.0f, 0.0f);
    }
    __syncthreads();                              // sorted lists + sentinel ready

    // ---- split-list composite: lane pairs (even=front, odd=back) ----
    const int pxi = tid >> 1;                     // pixel index 0..255
    const int px  = x0 + (pxi & (BLK_W - 1));
    const int py  = y0 + (pxi / BLK_W);
    const float fx = (float)px, fy = (float)py;
    const bool front = ((tid & 1) == 0);

    const int trips = (cnt + 1) >> 1;
    const int jbase = front ? 0 : trips;

    float T = 1.0f;
    unsigned long long crg = 0ull, cbd = 0ull;    // packed (cr,cg), (cb,dsum)

    #pragma unroll 4
    for (int i = 0; i < trips; i++) {
        int j = jbase + i;                        // back may touch sentinel once
        float4 A = sA[j];
        float dx = fx - A.x;
        float dy = fy - A.y;
        float d2 = fmaf(dx, dx, dy * dy);
        float a  = fex2(fmaf(A.z, d2, A.w));      // = op*gw <= 0.95 < 0.99
        float w  = a * T;
        ulonglong2 B = reinterpret_cast<const ulonglong2*>(sB)[j];
        unsigned long long ww;
        unsigned wu = __float_as_uint(w);
        asm("mov.b64 %0, {%1, %1};" : "=l"(ww) : "r"(wu));
        asm("fma.rn.f32x2 %0, %1, %2, %3;" : "=l"(crg) : "l"(B.x), "l"(ww), "l"(crg));
        asm("fma.rn.f32x2 %0, %1, %2, %3;" : "=l"(cbd) : "l"(B.y), "l"(ww), "l"(cbd));
        T = fmaf(-a, T, T);
    }

    float cr, cg, cb, dsum;
    { unsigned lo, hi;
      asm("mov.b64 {%0, %1}, %2;" : "=r"(lo), "=r"(hi) : "l"(crg));
      cr = __uint_as_float(lo); cg = __uint_as_float(hi);
      asm("mov.b64 {%0, %1}, %2;" : "=r"(lo), "=r"(hi) : "l"(cbd));
      cb = __uint_as_float(lo); dsum = __uint_as_float(hi); }

    // combine via lane shuffle: (C,T) o (C',T') = (C + T*C', T*T')
    float crb = __shfl_down_sync(0xffffffffu, cr,   1);
    float cgb = __shfl_down_sync(0xffffffffu, cg,   1);
    float cbb = __shfl_down_sync(0xffffffffu, cb,   1);
    float ddb = __shfl_down_sync(0xffffffffu, dsum, 1);
    float Tb  = __shfl_down_sync(0xffffffffu, T,    1);

    if (front) {
        cr   = fmaf(T, crb, cr);
        cg   = fmaf(T, cgb, cg);
        cb   = fmaf(T, cbb, cb);
        dsum = fmaf(T, ddb, dsum);
        T    = T * Tb;

        float acc = 1.0f - T;
        float bg  = T;
        int pix = py * IMG_W + px;
        out[pix*3 + 0] = fminf(fmaxf(cr + bg, 0.0f), 1.0f);
        out[pix*3 + 1] = fminf(fmaxf(cg + bg, 0.0f), 1.0f);
        out[pix*3 + 2] = fminf(fmaxf(cb + bg, 0.0f), 1.0f);
        out[IMG_W*IMG_H*3 + pix] = dsum;
        out[IMG_W*IMG_H*4 + pix] = acc;
    }
}

extern "C" void kernel_launch(void* const* d_in, const int* in_sizes, int n_in,
                              void* d_out, int out_size) {
    const float* means3d  = (const float*)d_in[0];
    const float* opacity  = (const float*)d_in[1];
    const float* scale3d  = (const float*)d_in[2];
    const float* features = (const float*)d_in[3];
    const float* viewm    = (const float*)d_in[4];
    const float* projm    = (const float*)d_in[5];
    float* out = (float*)d_out;

    k_fused<<<NBLK, NTHR>>>(means3d, opacity, scale3d, features, viewm, projm, out);
}